// round 12
// baseline (speedup 1.0000x reference)
#include <cuda_runtime.h>

// ---------------------------------------------------------------------------
// Greedy LSTM decoder, 128 sequential steps, single persistent kernel.
// Grid = 148 blocks x 1024 threads (<= SM count on B300/GB300, so all blocks
// are resident and a software grid barrier is safe).
// ---------------------------------------------------------------------------

#define NBLK 148
#define NTHR 1024
#define HDIM 1024
#define VOCAB 32000
#define ZCLEN 1088          // LIN(1024) + COND(64)
#define IDX_PER_BLK 7       // ceil(1024 / 148)
#define FC_SPLIT 20480      // fc rows kept L2-resident (80MB) + 32MB recurrent weights

static __device__ unsigned           g_bar;            // monotonic barrier counter
static __device__ unsigned long long g_packed[256];    // per-step argmax (enc(val)<<32 | ~idx)
static __device__ float              g_h[2][HDIM];     // double-buffered hidden state
static __device__ float              g_c[HDIM];        // cell state (single-owner per block)

__global__ void dec_init_kernel() {
    int t = threadIdx.x;
    if (t == 0) g_bar = 0u;
    for (int i = t; i < 256; i += blockDim.x) g_packed[i] = 0ull;
}

__device__ __forceinline__ float fsigm(float x) {
    return 1.0f / (1.0f + expf(-x));
}
__device__ __forceinline__ float ftanh_(float x) {
    // tanh via expf: robust even if tanhf maps to low-precision approx under fast-math
    float e = expf(-2.0f * fabsf(x));
    float r = (1.0f - e) / (1.0f + e);
    return copysignf(r, x);
}
__device__ __forceinline__ float warp_red(float v) {
#pragma unroll
    for (int o = 16; o; o >>= 1) v += __shfl_xor_sync(0xffffffffu, v, o);
    return v;
}

// Monotonic-count grid barrier. target = (#barriers so far) * gridDim.x
__device__ __forceinline__ void grid_barrier(unsigned target) {
    __threadfence();          // release: make this block's global writes visible
    __syncthreads();
    if (threadIdx.x == 0) {
        atomicAdd(&g_bar, 1u);
        while (*(volatile unsigned*)&g_bar < target) { /* spin (L2) */ }
        __threadfence();      // acquire-ish
    }
    __syncthreads();
}

__global__ void __launch_bounds__(NTHR, 1) dec_main_kernel(
    const float* __restrict__ z,   const float* __restrict__ cvec,
    const float* __restrict__ l1W, const float* __restrict__ l1b,
    const float* __restrict__ emb,
    const float* __restrict__ Wih, const float* __restrict__ Whh,
    const float* __restrict__ bih, const float* __restrict__ bhh,
    const float* __restrict__ fcW, const float* __restrict__ fcb,
    float* __restrict__ out, int T)
{
    __shared__ float xs[HDIM];
    __shared__ float hs[HDIM];
    __shared__ float gv[IDX_PER_BLK * 4];
    __shared__ unsigned long long wbest[32];
    __shared__ int s_tok;

    const int tid  = threadIdx.x;
    const int lane = tid & 31;
    const int wid  = tid >> 5;
    const int gw   = blockIdx.x * 32 + wid;       // global warp id
    const int nwarps = gridDim.x * 32;            // 4736
    unsigned ep = 0;

    // ---------------- prologue: h0 = l1W @ [z;c] + l1b ; c0 = 0 --------------
    for (int r = gw; r < HDIM; r += nwarps) {
        const float* row = l1W + (size_t)r * ZCLEN;
        float acc = 0.f;
        for (int k = lane; k < ZCLEN; k += 32) {
            float xv = (k < 1024) ? __ldg(&z[k]) : __ldg(&cvec[k - 1024]);
            acc += __ldg(&row[k]) * xv;
        }
        acc = warp_red(acc);
        if (lane == 0) g_h[0][r] = acc + __ldg(&l1b[r]);
    }
    if (blockIdx.x == 0) g_c[tid] = 0.f;   // NTHR == HDIM

    ep++; grid_barrier(ep * gridDim.x);

    const int start = blockIdx.x * IDX_PER_BLK;
    int nIdx = HDIM - start;
    if (nIdx > IDX_PER_BLK) nIdx = IDX_PER_BLK;
    if (nIdx < 0) nIdx = 0;

    for (int t = 0; t < T; t++) {
        const int pin  = t & 1;
        const int pout = pin ^ 1;

        // ---- token of previous step (grid-synced by last barrier) ----
        if (tid == 0) {
            int tok = 0;
            if (t > 0) {
                unsigned long long p = *(volatile unsigned long long*)&g_packed[t - 1];
                tok = (int)(~(unsigned)(p & 0xffffffffull));
            }
            s_tok = tok;
        }
        __syncthreads();
        {
            const int tok = s_tok;
            xs[tid] = fmaxf(__ldg(&emb[(size_t)tok * HDIM + tid]), 0.f);  // relu(emb)
            hs[tid] = __ldcg(&g_h[pin][tid]);                             // fresh from L2
        }
        __syncthreads();

        // ---- Phase A: gates = Wih@x + Whh@h + b ; fused LSTM update ----
        if (wid < nIdx * 4) {
            const int li  = wid >> 2;
            const int g   = wid & 3;
            const int row = g * HDIM + start + li;
            const float4* wi = (const float4*)(Wih + (size_t)row * HDIM);
            const float4* wh = (const float4*)(Whh + (size_t)row * HDIM);
            const float4* x4 = (const float4*)xs;
            const float4* h4 = (const float4*)hs;
            float acc = 0.f;
#pragma unroll
            for (int i = 0; i < 8; i++) {
                float4 a  = __ldg(&wi[lane + 32 * i]);
                float4 bx = x4[lane + 32 * i];
                acc += a.x * bx.x + a.y * bx.y + a.z * bx.z + a.w * bx.w;
                float4 c2 = __ldg(&wh[lane + 32 * i]);
                float4 dh = h4[lane + 32 * i];
                acc += c2.x * dh.x + c2.y * dh.y + c2.z * dh.z + c2.w * dh.w;
            }
            acc = warp_red(acc);
            if (lane == 0) gv[wid] = acc + __ldg(&bih[row]) + __ldg(&bhh[row]);
        }
        __syncthreads();
        if (tid < nIdx) {
            const int i = start + tid;
            float ig = fsigm(gv[tid * 4 + 0]);
            float fg = fsigm(gv[tid * 4 + 1]);
            float gg = ftanh_(gv[tid * 4 + 2]);
            float og = fsigm(gv[tid * 4 + 3]);
            float cn = fg * __ldcg(&g_c[i]) + ig * gg;
            g_c[i] = cn;
            g_h[pout][i] = og * ftanh_(cn);
        }

        ep++; grid_barrier(ep * gridDim.x);   // h_{t+1} complete

        // ---- Phase B: logits = fcW @ h_new + fcb ; argmax ----
        hs[tid] = __ldcg(&g_h[pout][tid]);
        __syncthreads();
        const float4* h4 = (const float4*)hs;
        float* orow = out + (size_t)t * VOCAB;
        unsigned long long best = 0ull;

        for (int v = gw; v < VOCAB; v += nwarps) {
            const float4* w4 = (const float4*)(fcW + (size_t)v * HDIM);
            float acc = 0.f;
            if (v < FC_SPLIT) {
#pragma unroll
                for (int i = 0; i < 8; i++) {
                    float4 a = __ldg(&w4[lane + 32 * i]);   // default policy: L2-resident
                    float4 b = h4[lane + 32 * i];
                    acc += a.x * b.x + a.y * b.y + a.z * b.z + a.w * b.w;
                }
            } else {
#pragma unroll
                for (int i = 0; i < 8; i++) {
                    float4 a = __ldcs(&w4[lane + 32 * i]);  // streaming: evict-first
                    float4 b = h4[lane + 32 * i];
                    acc += a.x * b.x + a.y * b.y + a.z * b.z + a.w * b.w;
                }
            }
            acc = warp_red(acc);
            if (lane == 0) {
                acc += __ldg(&fcb[v]);
                orow[v] = acc;
                // orderable encoding of float, ties -> smallest index (jnp.argmax)
                unsigned u = __float_as_uint(acc);
                u = (u & 0x80000000u) ? ~u : (u | 0x80000000u);
                unsigned long long pk =
                    ((unsigned long long)u << 32) | (unsigned)(~(unsigned)v);
                if (pk > best) best = pk;
            }
        }
        if (lane == 0) wbest[wid] = best;
        __syncthreads();
        if (wid == 0) {
            unsigned long long b2 = wbest[lane];
#pragma unroll
            for (int o = 16; o; o >>= 1) {
                unsigned long long ot = __shfl_xor_sync(0xffffffffu, b2, o);
                if (ot > b2) b2 = ot;
            }
            if (lane == 0) atomicMax(&g_packed[t], b2);
        }

        ep++; grid_barrier(ep * gridDim.x);   // token t final
    }
}

extern "C" void kernel_launch(void* const* d_in, const int* in_sizes, int n_in,
                              void* d_out, int out_size) {
    const float* z    = (const float*)d_in[0];
    const float* cvec = (const float*)d_in[1];
    const float* l1W  = (const float*)d_in[2];
    const float* l1b  = (const float*)d_in[3];
    const float* emb  = (const float*)d_in[4];
    const float* Wih  = (const float*)d_in[5];
    const float* Whh  = (const float*)d_in[6];
    const float* bih  = (const float*)d_in[7];
    const float* bhh  = (const float*)d_in[8];
    const float* fcW  = (const float*)d_in[9];
    const float* fcb  = (const float*)d_in[10];

    int T = out_size / VOCAB;
    if (T < 1) T = 1;
    if (T > 256) T = 256;

    dec_init_kernel<<<1, 256>>>();
    dec_main_kernel<<<NBLK, NTHR>>>(z, cvec, l1W, l1b, emb, Wih, Whh,
                                    bih, bhh, fcW, fcb, (float*)d_out, T);
}

// round 13
// speedup vs baseline: 1.9687x; 1.9687x over previous
#include <cuda_runtime.h>
#include <cuda_fp16.h>

// ---------------------------------------------------------------------------
// Greedy LSTM decoder, 128 sequential steps, single persistent kernel.
// fc_W converted once to fp16 scratch (64MB) -> steady working set (96MB)
// fits in the 126MB L2, so per-step weight reads are L2 hits.
// ---------------------------------------------------------------------------

#define NBLK 148
#define NTHR 1024
#define HDIM 1024
#define VOCAB 32000
#define ZCLEN 1088          // LIN(1024) + COND(64)
#define IDX_PER_BLK 7       // ceil(1024 / 148)

static __device__ unsigned           g_bar;            // monotonic barrier counter
static __device__ unsigned long long g_packed[256];    // per-step argmax (enc(val)<<32 | ~idx)
static __device__ float              g_h[2][HDIM];     // double-buffered hidden state
static __device__ float              g_c[HDIM];        // cell state
static __device__ __align__(16) __half g_fcW_h[(size_t)VOCAB * HDIM];  // 64MB fp16 scratch

__global__ void dec_init_kernel() {
    int t = threadIdx.x;
    if (t == 0) g_bar = 0u;
    for (int i = t; i < 256; i += blockDim.x) g_packed[i] = 0ull;
}

// fp32 -> fp16 conversion of fc_W (round-to-nearest). Runs every launch.
__global__ void cvt_fc_kernel(const float* __restrict__ fcW) {
    const int n4 = VOCAB * HDIM / 4;
    const float4* src = (const float4*)fcW;
    __half2* dst = (__half2*)g_fcW_h;
    for (int i = blockIdx.x * blockDim.x + threadIdx.x; i < n4;
         i += gridDim.x * blockDim.x) {
        float4 v = __ldcs(&src[i]);
        dst[2 * i + 0] = __floats2half2_rn(v.x, v.y);
        dst[2 * i + 1] = __floats2half2_rn(v.z, v.w);
    }
}

__device__ __forceinline__ float fsigm(float x) {
    return 1.0f / (1.0f + expf(-x));
}
__device__ __forceinline__ float ftanh_(float x) {
    float e = expf(-2.0f * fabsf(x));
    float r = (1.0f - e) / (1.0f + e);
    return copysignf(r, x);
}
__device__ __forceinline__ float warp_red(float v) {
#pragma unroll
    for (int o = 16; o; o >>= 1) v += __shfl_xor_sync(0xffffffffu, v, o);
    return v;
}

// Monotonic-count grid barrier.
__device__ __forceinline__ void grid_barrier(unsigned target) {
    __threadfence();
    __syncthreads();
    if (threadIdx.x == 0) {
        atomicAdd(&g_bar, 1u);
        while (*(volatile unsigned*)&g_bar < target) { }
        __threadfence();
    }
    __syncthreads();
}

__global__ void __launch_bounds__(NTHR, 1) dec_main_kernel(
    const float* __restrict__ z,   const float* __restrict__ cvec,
    const float* __restrict__ l1W, const float* __restrict__ l1b,
    const float* __restrict__ emb,
    const float* __restrict__ Wih, const float* __restrict__ Whh,
    const float* __restrict__ bih, const float* __restrict__ bhh,
    const float* __restrict__ fcb,
    float* __restrict__ out, int T)
{
    __shared__ float xs[HDIM];
    __shared__ float hs[HDIM];
    __shared__ float gv[IDX_PER_BLK * 4];
    __shared__ unsigned long long wbest[32];
    __shared__ int s_tok;

    const int tid  = threadIdx.x;
    const int lane = tid & 31;
    const int wid  = tid >> 5;
    const int gw   = blockIdx.x * 32 + wid;       // global warp id
    const int nwarps = gridDim.x * 32;            // 4736
    unsigned ep = 0;

    // ---------------- prologue: h0 = l1W @ [z;c] + l1b ; c0 = 0 --------------
    for (int r = gw; r < HDIM; r += nwarps) {
        const float* row = l1W + (size_t)r * ZCLEN;
        float acc = 0.f;
        for (int k = lane; k < ZCLEN; k += 32) {
            float xv = (k < 1024) ? __ldg(&z[k]) : __ldg(&cvec[k - 1024]);
            acc += __ldg(&row[k]) * xv;
        }
        acc = warp_red(acc);
        if (lane == 0) g_h[0][r] = acc + __ldg(&l1b[r]);
    }
    if (blockIdx.x == 0) g_c[tid] = 0.f;   // NTHR == HDIM

    ep++; grid_barrier(ep * gridDim.x);

    const int start = blockIdx.x * IDX_PER_BLK;
    int nIdx = HDIM - start;
    if (nIdx > IDX_PER_BLK) nIdx = IDX_PER_BLK;
    if (nIdx < 0) nIdx = 0;

    for (int t = 0; t < T; t++) {
        const int pin  = t & 1;
        const int pout = pin ^ 1;

        // ---- token of previous step ----
        if (tid == 0) {
            int tok = 0;
            if (t > 0) {
                unsigned long long p = *(volatile unsigned long long*)&g_packed[t - 1];
                tok = (int)(~(unsigned)(p & 0xffffffffull));
            }
            s_tok = tok;
        }
        __syncthreads();
        {
            const int tok = s_tok;
            xs[tid] = fmaxf(__ldg(&emb[(size_t)tok * HDIM + tid]), 0.f);
            hs[tid] = __ldcg(&g_h[pin][tid]);
        }
        __syncthreads();

        // ---- Phase A: gates = Wih@x + Whh@h + b ; fused LSTM update ----
        if (wid < nIdx * 4) {
            const int li  = wid >> 2;
            const int g   = wid & 3;
            const int row = g * HDIM + start + li;
            const float4* wi = (const float4*)(Wih + (size_t)row * HDIM);
            const float4* wh = (const float4*)(Whh + (size_t)row * HDIM);
            const float4* x4 = (const float4*)xs;
            const float4* h4 = (const float4*)hs;
            float acc = 0.f;
#pragma unroll
            for (int i = 0; i < 8; i++) {
                float4 a  = __ldg(&wi[lane + 32 * i]);
                float4 bx = x4[lane + 32 * i];
                acc += a.x * bx.x + a.y * bx.y + a.z * bx.z + a.w * bx.w;
                float4 c2 = __ldg(&wh[lane + 32 * i]);
                float4 dh = h4[lane + 32 * i];
                acc += c2.x * dh.x + c2.y * dh.y + c2.z * dh.z + c2.w * dh.w;
            }
            acc = warp_red(acc);
            if (lane == 0) gv[wid] = acc + __ldg(&bih[row]) + __ldg(&bhh[row]);
        }
        __syncthreads();
        if (tid < nIdx) {
            const int i = start + tid;
            float ig = fsigm(gv[tid * 4 + 0]);
            float fg = fsigm(gv[tid * 4 + 1]);
            float gg = ftanh_(gv[tid * 4 + 2]);
            float og = fsigm(gv[tid * 4 + 3]);
            float cn = fg * __ldcg(&g_c[i]) + ig * gg;
            g_c[i] = cn;
            g_h[pout][i] = og * ftanh_(cn);
        }

        ep++; grid_barrier(ep * gridDim.x);   // h_{t+1} complete

        // ---- Phase B: logits = fcW(fp16) @ h_new + fcb ; argmax ----
        hs[tid] = __ldcg(&g_h[pout][tid]);
        __syncthreads();
        const float4* h4 = (const float4*)hs;
        float* orow = out + (size_t)t * VOCAB;
        unsigned long long best = 0ull;

        // 2 consecutive rows per warp iteration: 8 independent 16B loads in flight
        for (int v = gw * 2; v < VOCAB; v += nwarps * 2) {
            const uint4* w0 = (const uint4*)(g_fcW_h + (size_t)v * HDIM);
            const uint4* w1 = (const uint4*)(g_fcW_h + (size_t)(v + 1) * HDIM);
            float a0 = 0.f, a1 = 0.f;
#pragma unroll
            for (int i = 0; i < 4; i++) {
                uint4 p = __ldg(&w0[lane + 32 * i]);
                uint4 q = __ldg(&w1[lane + 32 * i]);
                float4 hA = h4[(lane + 32 * i) * 2 + 0];
                float4 hB = h4[(lane + 32 * i) * 2 + 1];
                float2 f;
                f = __half22float2(*(__half2*)&p.x); a0 += f.x * hA.x + f.y * hA.y;
                f = __half22float2(*(__half2*)&p.y); a0 += f.x * hA.z + f.y * hA.w;
                f = __half22float2(*(__half2*)&p.z); a0 += f.x * hB.x + f.y * hB.y;
                f = __half22float2(*(__half2*)&p.w); a0 += f.x * hB.z + f.y * hB.w;
                f = __half22float2(*(__half2*)&q.x); a1 += f.x * hA.x + f.y * hA.y;
                f = __half22float2(*(__half2*)&q.y); a1 += f.x * hA.z + f.y * hA.w;
                f = __half22float2(*(__half2*)&q.z); a1 += f.x * hB.x + f.y * hB.y;
                f = __half22float2(*(__half2*)&q.w); a1 += f.x * hB.z + f.y * hB.w;
            }
            a0 = warp_red(a0);
            a1 = warp_red(a1);
            if (lane == 0) {
                a0 += __ldg(&fcb[v]);
                a1 += __ldg(&fcb[v + 1]);
                __stcs(&orow[v], a0);       // streaming store: keep L2 for weights
                __stcs(&orow[v + 1], a1);
                unsigned u0 = __float_as_uint(a0);
                u0 = (u0 & 0x80000000u) ? ~u0 : (u0 | 0x80000000u);
                unsigned long long p0 =
                    ((unsigned long long)u0 << 32) | (unsigned)(~(unsigned)v);
                unsigned u1 = __float_as_uint(a1);
                u1 = (u1 & 0x80000000u) ? ~u1 : (u1 | 0x80000000u);
                unsigned long long p1 =
                    ((unsigned long long)u1 << 32) | (unsigned)(~(unsigned)(v + 1));
                if (p0 > best) best = p0;
                if (p1 > best) best = p1;
            }
        }
        if (lane == 0) wbest[wid] = best;
        __syncthreads();
        if (wid == 0) {
            unsigned long long b2 = wbest[lane];
#pragma unroll
            for (int o = 16; o; o >>= 1) {
                unsigned long long ot = __shfl_xor_sync(0xffffffffu, b2, o);
                if (ot > b2) b2 = ot;
            }
            if (lane == 0) atomicMax(&g_packed[t], b2);
        }

        ep++; grid_barrier(ep * gridDim.x);   // token t final
    }
}

extern "C" void kernel_launch(void* const* d_in, const int* in_sizes, int n_in,
                              void* d_out, int out_size) {
    const float* z    = (const float*)d_in[0];
    const float* cvec = (const float*)d_in[1];
    const float* l1W  = (const float*)d_in[2];
    const float* l1b  = (const float*)d_in[3];
    const float* emb  = (const float*)d_in[4];
    const float* Wih  = (const float*)d_in[5];
    const float* Whh  = (const float*)d_in[6];
    const float* bih  = (const float*)d_in[7];
    const float* bhh  = (const float*)d_in[8];
    const float* fcW  = (const float*)d_in[9];
    const float* fcb  = (const float*)d_in[10];

    int T = out_size / VOCAB;
    if (T < 1) T = 1;
    if (T > 256) T = 256;

    dec_init_kernel<<<1, 256>>>();
    cvt_fc_kernel<<<4096, 256>>>(fcW);
    dec_main_kernel<<<NBLK, NTHR>>>(z, cvec, l1W, l1b, emb, Wih, Whh,
                                    bih, bhh, fcb, (float*)d_out, T);
}

// round 14
// speedup vs baseline: 2.2074x; 1.1212x over previous
#include <cuda_runtime.h>
#include <cuda_fp16.h>

// ---------------------------------------------------------------------------
// Greedy LSTM decoder, 128 sequential steps, single persistent kernel.
// fc_W, W_ih, W_hh converted once to fp16 scratch (64+8+8 = 80MB) -> steady
// working set fits the 126MB L2, so per-step weight reads are L2 hits.
// ---------------------------------------------------------------------------

#define NBLK 148
#define NTHR 1024
#define HDIM 1024
#define VOCAB 32000
#define ZCLEN 1088          // LIN(1024) + COND(64)
#define IDX_PER_BLK 7       // ceil(1024 / 148)

static __device__ unsigned           g_bar;            // monotonic barrier counter
static __device__ unsigned long long g_packed[256];    // per-step argmax (enc(val)<<32 | ~idx)
static __device__ float              g_h[2][HDIM];     // double-buffered hidden state
static __device__ float              g_c[HDIM];        // cell state
static __device__ __align__(16) __half g_fcW_h[(size_t)VOCAB * HDIM]; // 64MB
static __device__ __align__(16) __half g_Wih_h[(size_t)4 * HDIM * HDIM]; // 8MB
static __device__ __align__(16) __half g_Whh_h[(size_t)4 * HDIM * HDIM]; // 8MB

__global__ void dec_init_kernel() {
    int t = threadIdx.x;
    if (t == 0) g_bar = 0u;
    for (int i = t; i < 256; i += blockDim.x) g_packed[i] = 0ull;
}

// fp32 -> fp16 conversion (round-to-nearest), generic.
__global__ void cvt_kernel(const float* __restrict__ src_, __half* __restrict__ dst_,
                           int n4) {
    const float4* src = (const float4*)src_;
    __half2* dst = (__half2*)dst_;
    for (int i = blockIdx.x * blockDim.x + threadIdx.x; i < n4;
         i += gridDim.x * blockDim.x) {
        float4 v = __ldcs(&src[i]);
        dst[2 * i + 0] = __floats2half2_rn(v.x, v.y);
        dst[2 * i + 1] = __floats2half2_rn(v.z, v.w);
    }
}

__device__ __forceinline__ float fsigm(float x) {
    return 1.0f / (1.0f + expf(-x));
}
__device__ __forceinline__ float ftanh_(float x) {
    float e = expf(-2.0f * fabsf(x));
    float r = (1.0f - e) / (1.0f + e);
    return copysignf(r, x);
}
__device__ __forceinline__ float warp_red(float v) {
#pragma unroll
    for (int o = 16; o; o >>= 1) v += __shfl_xor_sync(0xffffffffu, v, o);
    return v;
}

// Monotonic-count grid barrier.
__device__ __forceinline__ void grid_barrier(unsigned target) {
    __threadfence();
    __syncthreads();
    if (threadIdx.x == 0) {
        atomicAdd(&g_bar, 1u);
        while (*(volatile unsigned*)&g_bar < target) { }
        __threadfence();
    }
    __syncthreads();
}

// dot of 8 fp16 weights (uint4 half) against 16 fp32 activations helper:
// handled inline below.

__global__ void __launch_bounds__(NTHR, 1) dec_main_kernel(
    const float* __restrict__ z,   const float* __restrict__ cvec,
    const float* __restrict__ l1W, const float* __restrict__ l1b,
    const float* __restrict__ emb,
    const float* __restrict__ bih, const float* __restrict__ bhh,
    const float* __restrict__ fcb,
    float* __restrict__ out, int T)
{
    __shared__ float xs[HDIM];
    __shared__ float hs[HDIM];
    __shared__ float gv[IDX_PER_BLK * 4];
    __shared__ unsigned long long wbest[32];
    __shared__ int s_tok;

    const int tid  = threadIdx.x;
    const int lane = tid & 31;
    const int wid  = tid >> 5;
    const int gw   = blockIdx.x * 32 + wid;       // global warp id
    const int nwarps = gridDim.x * 32;            // 4736
    unsigned ep = 0;

    // ---------------- prologue: h0 = l1W @ [z;c] + l1b ; c0 = 0 --------------
    for (int r = gw; r < HDIM; r += nwarps) {
        const float* row = l1W + (size_t)r * ZCLEN;
        float acc = 0.f;
        for (int k = lane; k < ZCLEN; k += 32) {
            float xv = (k < 1024) ? __ldg(&z[k]) : __ldg(&cvec[k - 1024]);
            acc += __ldg(&row[k]) * xv;
        }
        acc = warp_red(acc);
        if (lane == 0) g_h[0][r] = acc + __ldg(&l1b[r]);
    }
    if (blockIdx.x == 0) g_c[tid] = 0.f;   // NTHR == HDIM

    ep++; grid_barrier(ep * gridDim.x);

    const int start = blockIdx.x * IDX_PER_BLK;
    int nIdx = HDIM - start;
    if (nIdx > IDX_PER_BLK) nIdx = IDX_PER_BLK;
    if (nIdx < 0) nIdx = 0;

    for (int t = 0; t < T; t++) {
        const int pin  = t & 1;
        const int pout = pin ^ 1;

        // ---- token of previous step ----
        if (tid == 0) {
            int tok = 0;
            if (t > 0) {
                unsigned long long p = *(volatile unsigned long long*)&g_packed[t - 1];
                tok = (int)(~(unsigned)(p & 0xffffffffull));
            }
            s_tok = tok;
        }
        __syncthreads();
        {
            const int tok = s_tok;
            xs[tid] = fmaxf(__ldg(&emb[(size_t)tok * HDIM + tid]), 0.f);
            hs[tid] = __ldcg(&g_h[pin][tid]);
        }
        __syncthreads();

        // ---- Phase A: gates = Wih@x + Whh@h + b (fp16 weights) ----
        if (wid < nIdx * 4) {
            const int li  = wid >> 2;
            const int g   = wid & 3;
            const int row = g * HDIM + start + li;
            const uint4* wi = (const uint4*)(g_Wih_h + (size_t)row * HDIM);
            const uint4* wh = (const uint4*)(g_Whh_h + (size_t)row * HDIM);
            const float4* x4 = (const float4*)xs;
            const float4* h4 = (const float4*)hs;
            float acc = 0.f;
#pragma unroll
            for (int i = 0; i < 4; i++) {
                uint4 p = __ldg(&wi[lane + 32 * i]);     // 8 halves of Wih row
                uint4 q = __ldg(&wh[lane + 32 * i]);     // 8 halves of Whh row
                const int b = (lane + 32 * i) * 2;       // float4 index into acts
                float4 xA = x4[b], xB = x4[b + 1];
                float4 hA = h4[b], hB = h4[b + 1];
                float2 f;
                f = __half22float2(*(__half2*)&p.x); acc += f.x * xA.x + f.y * xA.y;
                f = __half22float2(*(__half2*)&p.y); acc += f.x * xA.z + f.y * xA.w;
                f = __half22float2(*(__half2*)&p.z); acc += f.x * xB.x + f.y * xB.y;
                f = __half22float2(*(__half2*)&p.w); acc += f.x * xB.z + f.y * xB.w;
                f = __half22float2(*(__half2*)&q.x); acc += f.x * hA.x + f.y * hA.y;
                f = __half22float2(*(__half2*)&q.y); acc += f.x * hA.z + f.y * hA.w;
                f = __half22float2(*(__half2*)&q.z); acc += f.x * hB.x + f.y * hB.y;
                f = __half22float2(*(__half2*)&q.w); acc += f.x * hB.z + f.y * hB.w;
            }
            acc = warp_red(acc);
            if (lane == 0) gv[wid] = acc + __ldg(&bih[row]) + __ldg(&bhh[row]);
        }
        __syncthreads();
        if (tid < nIdx) {
            const int i = start + tid;
            float ig = fsigm(gv[tid * 4 + 0]);
            float fg = fsigm(gv[tid * 4 + 1]);
            float gg = ftanh_(gv[tid * 4 + 2]);
            float og = fsigm(gv[tid * 4 + 3]);
            float cn = fg * __ldcg(&g_c[i]) + ig * gg;
            g_c[i] = cn;
            g_h[pout][i] = og * ftanh_(cn);
        }

        ep++; grid_barrier(ep * gridDim.x);   // h_{t+1} complete

        // ---- Phase B: logits = fcW(fp16) @ h_new + fcb ; argmax ----
        hs[tid] = __ldcg(&g_h[pout][tid]);
        __syncthreads();
        const float4* h4 = (const float4*)hs;
        float* orow = out + (size_t)t * VOCAB;
        unsigned long long best = 0ull;

        // 2 consecutive rows per warp iteration: 8 independent 16B loads in flight
        for (int v = gw * 2; v < VOCAB; v += nwarps * 2) {
            const uint4* w0 = (const uint4*)(g_fcW_h + (size_t)v * HDIM);
            const uint4* w1 = (const uint4*)(g_fcW_h + (size_t)(v + 1) * HDIM);
            float a0 = 0.f, a1 = 0.f;
#pragma unroll
            for (int i = 0; i < 4; i++) {
                uint4 p = __ldg(&w0[lane + 32 * i]);
                uint4 q = __ldg(&w1[lane + 32 * i]);
                const int b = (lane + 32 * i) * 2;
                float4 hA = h4[b], hB = h4[b + 1];
                float2 f;
                f = __half22float2(*(__half2*)&p.x); a0 += f.x * hA.x + f.y * hA.y;
                f = __half22float2(*(__half2*)&p.y); a0 += f.x * hA.z + f.y * hA.w;
                f = __half22float2(*(__half2*)&p.z); a0 += f.x * hB.x + f.y * hB.y;
                f = __half22float2(*(__half2*)&p.w); a0 += f.x * hB.z + f.y * hB.w;
                f = __half22float2(*(__half2*)&q.x); a1 += f.x * hA.x + f.y * hA.y;
                f = __half22float2(*(__half2*)&q.y); a1 += f.x * hA.z + f.y * hA.w;
                f = __half22float2(*(__half2*)&q.z); a1 += f.x * hB.x + f.y * hB.y;
                f = __half22float2(*(__half2*)&q.w); a1 += f.x * hB.z + f.y * hB.w;
            }
            a0 = warp_red(a0);
            a1 = warp_red(a1);
            if (lane == 0) {
                a0 += __ldg(&fcb[v]);
                a1 += __ldg(&fcb[v + 1]);
                __stcs(&orow[v], a0);       // streaming store: keep L2 for weights
                __stcs(&orow[v + 1], a1);
                unsigned u0 = __float_as_uint(a0);
                u0 = (u0 & 0x80000000u) ? ~u0 : (u0 | 0x80000000u);
                unsigned long long p0 =
                    ((unsigned long long)u0 << 32) | (unsigned)(~(unsigned)v);
                unsigned u1 = __float_as_uint(a1);
                u1 = (u1 & 0x80000000u) ? ~u1 : (u1 | 0x80000000u);
                unsigned long long p1 =
                    ((unsigned long long)u1 << 32) | (unsigned)(~(unsigned)(v + 1));
                if (p0 > best) best = p0;
                if (p1 > best) best = p1;
            }
        }
        if (lane == 0) wbest[wid] = best;
        __syncthreads();
        if (wid == 0) {
            unsigned long long b2 = wbest[lane];
#pragma unroll
            for (int o = 16; o; o >>= 1) {
                unsigned long long ot = __shfl_xor_sync(0xffffffffu, b2, o);
                if (ot > b2) b2 = ot;
            }
            if (lane == 0) atomicMax(&g_packed[t], b2);
        }

        ep++; grid_barrier(ep * gridDim.x);   // token t final
    }
}

extern "C" void kernel_launch(void* const* d_in, const int* in_sizes, int n_in,
                              void* d_out, int out_size) {
    const float* z    = (const float*)d_in[0];
    const float* cvec = (const float*)d_in[1];
    const float* l1W  = (const float*)d_in[2];
    const float* l1b  = (const float*)d_in[3];
    const float* emb  = (const float*)d_in[4];
    const float* Wih  = (const float*)d_in[5];
    const float* Whh  = (const float*)d_in[6];
    const float* bih  = (const float*)d_in[7];
    const float* bhh  = (const float*)d_in[8];
    const float* fcW  = (const float*)d_in[9];
    const float* fcb  = (const float*)d_in[10];

    int T = out_size / VOCAB;
    if (T < 1) T = 1;
    if (T > 256) T = 256;

    __half* d_fc;  cudaGetSymbolAddress((void**)&d_fc,  g_fcW_h);
    __half* d_wih; cudaGetSymbolAddress((void**)&d_wih, g_Wih_h);
    __half* d_whh; cudaGetSymbolAddress((void**)&d_whh, g_Whh_h);

    dec_init_kernel<<<1, 256>>>();
    cvt_kernel<<<4096, 256>>>(fcW, d_fc, VOCAB * HDIM / 4);
    cvt_kernel<<<1024, 256>>>(Wih, d_wih, 4 * HDIM * HDIM / 4);
    cvt_kernel<<<1024, 256>>>(Whh, d_whh, 4 * HDIM * HDIM / 4);
    dec_main_kernel<<<NBLK, NTHR>>>(z, cvec, l1W, l1b, emb,
                                    bih, bhh, fcb, (float*)d_out, T);
}